// round 1
// baseline (speedup 1.0000x reference)
#include <cuda_runtime.h>
#include <cstdint>

// VQVAE_8658654068982: nearest-codebook quantization.
// z: [131072, 64] fp32 (d_in[0]), codebook: [512, 64] fp32 (d_in[1]).
// out: (x_recon, z_quantized) both = codebook[argmin_j ||z-e_j||^2], concatenated.

#define Dm 64
#define Kc 512
#define CHUNK 128
#define THREADS 256
#define MARGIN 1e-4f

// Exact (sequential fp32) ||e_j||^2, emulating jnp.sum(codebook*codebook, axis=1):
// products rounded (__fmul_rn) then sequentially added (__fadd_rn).
__device__ float g_ee[Kc];

__global__ void ee_kernel(const float* __restrict__ cb) {
    int j = blockIdx.x * blockDim.x + threadIdx.x;
    if (j < Kc) {
        const float* e = cb + j * Dm;
        float s = 0.0f;
#pragma unroll
        for (int k = 0; k < Dm; ++k) s = __fadd_rn(s, __fmul_rn(e[k], e[k]));
        g_ee[j] = s;
    }
}

__device__ __forceinline__ unsigned long long fma2(unsigned long long a,
                                                   unsigned long long b,
                                                   unsigned long long c) {
    unsigned long long d;
    asm("fma.rn.f32x2 %0, %1, %2, %3;" : "=l"(d) : "l"(a), "l"(b), "l"(c));
    return d;
}
__device__ __forceinline__ float2 unpack2(unsigned long long a) {
    float2 r;
    asm("mov.b64 {%0, %1}, %2;" : "=f"(r.x), "=f"(r.y) : "l"(a));
    return r;
}

__global__ void __launch_bounds__(THREADS, 2)
vq_kernel(const float* __restrict__ z, const float* __restrict__ cb,
          float* __restrict__ out, int half) {
    __shared__ float sh[CHUNK * Dm + CHUNK];
    float* sh_ee = sh + CHUNK * Dm;
    const int row = blockIdx.x * THREADS + threadIdx.x;

    // z row in registers as 16 x ulonglong2 (= 64 fp32, packed for f32x2 FMA).
    ulonglong2 za[16];
    {
        const ulonglong2* zr = (const ulonglong2*)(z + (size_t)row * Dm);
#pragma unroll
        for (int i = 0; i < 16; ++i) za[i] = zr[i];
    }

    // zz: exact sequential fp32 emulation of jnp.sum(zf*zf, axis=1).
    float zz = 0.0f;
#pragma unroll
    for (int i = 0; i < 16; ++i) {
        float2 a = unpack2(za[i].x), b = unpack2(za[i].y);
        zz = __fadd_rn(zz, __fmul_rn(a.x, a.x));
        zz = __fadd_rn(zz, __fmul_rn(a.y, a.y));
        zz = __fadd_rn(zz, __fmul_rn(b.x, b.x));
        zz = __fadd_rn(zz, __fmul_rn(b.y, b.y));
    }

    // ---- Pass 1: fast packed-f32x2 scores, keep top-4 (value, index) ----
    float s1 = 1e30f, s2 = 1e30f, s3 = 1e30f, s4 = 1e30f;
    int i1 = 0, i2 = 0, i3 = 0, i4 = 0;

    for (int c = 0; c < Kc / CHUNK; ++c) {
        __syncthreads();
        {
            const float4* src = (const float4*)(cb + c * CHUNK * Dm);
            float4* dst = (float4*)sh;
            for (int i = threadIdx.x; i < CHUNK * Dm / 4; i += THREADS) dst[i] = src[i];
            if (threadIdx.x < CHUNK) sh_ee[threadIdx.x] = g_ee[c * CHUNK + threadIdx.x];
        }
        __syncthreads();
#pragma unroll 2
        for (int j = 0; j < CHUNK; ++j) {
            const ulonglong2* e2 = (const ulonglong2*)(sh + j * Dm);
            unsigned long long a0 = 0ull, a1 = 0ull, a2 = 0ull, a3 = 0ull;
#pragma unroll
            for (int k = 0; k < 16; k += 2) {
                ulonglong2 v0 = e2[k];
                ulonglong2 v1 = e2[k + 1];
                a0 = fma2(za[k].x, v0.x, a0);
                a1 = fma2(za[k].y, v0.y, a1);
                a2 = fma2(za[k + 1].x, v1.x, a2);
                a3 = fma2(za[k + 1].y, v1.y, a3);
            }
            float2 p0 = unpack2(a0), p1 = unpack2(a1), p2 = unpack2(a2), p3 = unpack2(a3);
            float dot = ((p0.x + p0.y) + (p1.x + p1.y)) + ((p2.x + p2.y) + (p3.x + p3.y));
            float s = (zz + sh_ee[j]) - 2.0f * dot;
            int jj = c * CHUNK + j;
            if (s < s4) {
                if (s < s1)      { s4 = s3; i4 = i3; s3 = s2; i3 = i2; s2 = s1; i2 = i1; s1 = s; i1 = jj; }
                else if (s < s2) { s4 = s3; i4 = i3; s3 = s2; i3 = i2; s2 = s;  i2 = jj; }
                else if (s < s3) { s4 = s3; i4 = i3; s3 = s;  i3 = jj; }
                else             { s4 = s;  i4 = jj; }
            }
        }
    }

    // ---- Pass 2: if runner-up within margin, exact fp32 emulation of the
    // reference op chain on the candidates; first-index tie-break (jnp.argmin) ----
    int bidx = i1;
    if (s2 - s1 <= MARGIN) {
        float best = 1e30f;
        int bi = 0x7fffffff;
        float cs[4] = {s1, s2, s3, s4};
        int ci[4] = {i1, i2, i3, i4};
#pragma unroll
        for (int t = 0; t < 4; ++t) {
            if (cs[t] - s1 <= MARGIN) {
                const float* e = cb + (size_t)ci[t] * Dm;
                float dot = 0.0f;
#pragma unroll
                for (int k = 0; k < 16; ++k) {
                    float2 a = unpack2(za[k].x), b = unpack2(za[k].y);
                    dot = __fmaf_rn(a.x, __ldg(e + 4 * k + 0), dot);
                    dot = __fmaf_rn(a.y, __ldg(e + 4 * k + 1), dot);
                    dot = __fmaf_rn(b.x, __ldg(e + 4 * k + 2), dot);
                    dot = __fmaf_rn(b.y, __ldg(e + 4 * k + 3), dot);
                }
                // d = fl(fl(zz + ee) - fl(2*dot)); 2*dot and its negation are exact.
                float sx = __fadd_rn(__fadd_rn(zz, g_ee[ci[t]]), __fmul_rn(-2.0f, dot));
                if (sx < best || (sx == best && ci[t] < bi)) { best = sx; bi = ci[t]; }
            }
        }
        bidx = bi;
    }

    // ---- Gather + write both tuple outputs ----
    {
        const float4* e4 = (const float4*)(cb + (size_t)bidx * Dm);
        float4* o1 = (float4*)(out + (size_t)row * Dm);
#pragma unroll
        for (int i = 0; i < 16; ++i) o1[i] = e4[i];
        if (half > 0) {
            float4* o2 = (float4*)(out + (size_t)half + (size_t)row * Dm);
#pragma unroll
            for (int i = 0; i < 16; ++i) o2[i] = e4[i];
        }
    }
}

extern "C" void kernel_launch(void* const* d_in, const int* in_sizes, int n_in,
                              void* d_out, int out_size) {
    const float* z = (const float*)d_in[0];
    const float* cb = (const float*)d_in[1];
    float* out = (float*)d_out;
    const int N = in_sizes[0] / Dm;             // 131072 rows
    // Tuple output (x_recon, z_quantized): duplicate halves. If the harness
    // only exposes a single tensor, write once.
    int half = (out_size >= 2 * N * Dm) ? (out_size / 2) : 0;

    ee_kernel<<<(Kc + 255) / 256, 256>>>(cb);
    vq_kernel<<<N / THREADS, THREADS>>>(z, cb, out, half);
}